// round 9
// baseline (speedup 1.0000x reference)
#include <cuda_runtime.h>
#include <cuda_bf16.h>
#include <cstdint>

#define BS 16
#define NN 512
#define DD 256
#define RR 2
#define M_TOTAL (BS * NN)           // 8192
#define K_TOTAL (3 * DD)            // 768
#define BKT 16                      // GEMM K-tile
#define NT (K_TOTAL / BKT)          // 48 tiles
#define STG 3                       // GEMM cp.async stages
#define ACAT_L ((size_t)M_TOTAL * K_TOTAL)   // per-layer A size
#define W_L    ((size_t)K_TOTAL * DD)        // per-layer W size

#define TJ 64                       // agg: targets per block
#define SI 16                       // agg: staged sources per tile
#define NTI (NN / SI)               // 32 source tiles

// Scratch (no allocations allowed).
__device__ __align__(16) unsigned char g_maskT[(size_t)BS * NN * NN];  // [b][j][i]
__device__ __align__(16) uint32_t g_bits[BS * NN][RR][NN / 32];        // per (b,j): source bitmaps
__device__ float g_inv[RR][BS * NN];
__device__ __align__(16) uint32_t g_acat[2 * ACAT_L];   // tf32 [layer][m][768] = [x|agg0|agg1]
__device__ __align__(16) uint32_t g_w[2 * W_L];         // tf32 [layer][768][256]
__device__ __align__(16) float g_h[(size_t)BS * NN * DD];   // layer-1 output (fp32)

__device__ __forceinline__ uint32_t f2tf32(float f) {
    uint32_t u;
    asm("cvt.rna.tf32.f32 %0, %1;" : "=r"(u) : "f"(f));
    return u;
}

__device__ __forceinline__ void cp16(uint32_t dst, const void* src) {
    asm volatile("cp.async.cg.shared.global [%0], [%1], 16;"
                 :: "r"(dst), "l"(src));
}

// ---------------------------------------------------------------------------
// Kernel 1: packed transposed masks (adjacency is int32 on device — JAX
// downcasts int64). bit0 = punct (punct==1 && aug!=1), bit1 = aug (aug==1).
// ---------------------------------------------------------------------------
__global__ void build_masks_kernel(const int* __restrict__ aug,
                                   const int* __restrict__ punct) {
    __shared__ unsigned char tile[32][33];
    const int b  = blockIdx.z;
    const int i0 = blockIdx.y * 32;
    const int j0 = blockIdx.x * 32;
    const int tx = threadIdx.x;   // 32
    const int ty = threadIdx.y;   // 8
    const size_t base = (size_t)b * NN * NN;

    #pragma unroll
    for (int s = 0; s < 4; s++) {
        const int ii = ty + s * 8;
        const size_t idx = base + (size_t)(i0 + ii) * NN + (j0 + tx);
        const int a = aug[idx];
        const int p = punct[idx];
        tile[ii][tx] = (a == 1) ? (unsigned char)2
                                : ((p == 1) ? (unsigned char)1 : (unsigned char)0);
    }
    __syncthreads();
    #pragma unroll
    for (int s = 0; s < 4; s++) {
        const int jj = ty + s * 8;
        g_maskT[base + (size_t)(j0 + jj) * NN + (i0 + tx)] = tile[tx][jj];
    }
}

// ---------------------------------------------------------------------------
// Kernel 2: per-(b,j) source bitmaps + inverse degrees. One warp per target.
// ---------------------------------------------------------------------------
__global__ void __launch_bounds__(32)
build_bits_kernel() {
    const int j = blockIdx.x;
    const int b = blockIdx.y;
    const int lane = threadIdx.x;
    const size_t o = (size_t)b * NN + j;
    const unsigned char* __restrict__ row = g_maskT + o * NN;

    int c0 = 0, c1 = 0;
    #pragma unroll 4
    for (int s = 0; s < NN; s += 32) {
        const unsigned char m = row[s + lane];
        const unsigned b0 = __ballot_sync(0xffffffffu, m & 1);
        const unsigned b1 = __ballot_sync(0xffffffffu, m & 2);
        if (lane == 0) {
            g_bits[o][0][s >> 5] = b0;
            g_bits[o][1][s >> 5] = b1;
        }
        c0 += __popc(b0);
        c1 += __popc(b1);
    }
    if (lane == 0) {
        g_inv[0][o] = 1.0f / (float)max(c0, 1);
        g_inv[1][o] = 1.0f / (float)max(c1, 1);
    }
}

// ---------------------------------------------------------------------------
// Kernel 3: convert x and both layers' weights to tf32, into the concat
// layouts g_acat[0] (seg0) and g_w[0..1]. Grid-stride over float4 items.
// ---------------------------------------------------------------------------
#define XF4 (M_TOTAL * DD / 4)           // 524288
#define WF4L (K_TOTAL * DD / 4)          // 49152 per layer
#define ROOTF4 (DD * DD / 4)             // 16384

__global__ void cvt_inputs_kernel(const float* __restrict__ x,
                                  const float* __restrict__ wroot1,
                                  const float* __restrict__ wrel1,
                                  const float* __restrict__ wroot2,
                                  const float* __restrict__ wrel2) {
    const int total = XF4 + 2 * WF4L;
    for (int idx = blockIdx.x * blockDim.x + threadIdx.x; idx < total;
         idx += gridDim.x * blockDim.x) {
        float4 v;
        uint32_t* dst;
        if (idx < XF4) {
            const int m = idx >> 6;            // DD/4 = 64
            const int dq = idx & 63;
            v = ((const float4*)x)[idx];
            dst = g_acat + (size_t)m * K_TOTAL + dq * 4;
        } else {
            const int j = idx - XF4;
            const int L = j / WF4L;
            const int j2 = j - L * WF4L;
            const float4* src = (j2 < ROOTF4)
                ? ((const float4*)(L ? wroot2 : wroot1)) + j2
                : ((const float4*)(L ? wrel2 : wrel1)) + (j2 - ROOTF4);
            v = *src;
            dst = g_w + (size_t)L * W_L + (size_t)j2 * 4;
        }
        uint4 u;
        u.x = f2tf32(v.x); u.y = f2tf32(v.y);
        u.z = f2tf32(v.z); u.w = f2tf32(v.w);
        *(uint4*)dst = u;
    }
}

// ---------------------------------------------------------------------------
// Kernel 4: source-staged sparse mean-aggregation.
// Block = (j-tile of TJ=64, b), 512 threads. Thread t = (jl = t/8, cg = t%8);
// thread owns float4 slots {cg + 8q : q=0..7} of the 256-ch row (bank-safe).
// Source rows staged through shared in SI=16 tiles (cp.async double buffer);
// per-j occupancy comes from 16-bit slices of the bitmaps.
// Writes tf32 directly into g_acat[layer] segments 1 and 2.
// ---------------------------------------------------------------------------
__global__ void __launch_bounds__(512)
aggregate_kernel(const float* __restrict__ x, int layer) {
    const int jt = blockIdx.x;    // 0..NN/TJ-1
    const int b  = blockIdx.y;
    const int t  = threadIdx.x;   // 0..511
    const int jl = t >> 3;        // 0..63
    const int cg = t & 7;         // 0..7

    __shared__ float4   stg[2][SI][DD / 4];      // 32 KB
    __shared__ uint32_t sbits[TJ][RR][NN / 32];  // 8 KB
    __shared__ float    sinv[TJ][RR];

    const size_t obase = (size_t)b * NN + jt * TJ;

    // load bitmaps + inv for this j-tile
    for (int k = t; k < TJ * 2 * (NN / 32); k += 512) {
        const int jj = k >> 5;
        const int w  = k & 31;
        sbits[jj][w >> 4][w & 15] = g_bits[obase + jj][w >> 4][w & 15];
    }
    if (t < TJ * RR)
        sinv[t >> 1][t & 1] = g_inv[t & 1][obase + (t >> 1)];

    const float* __restrict__ xb =
        (layer ? (const float*)g_h : x) + (size_t)b * NN * DD;
    const uint32_t stg_base = (uint32_t)__cvta_generic_to_shared(stg);

    auto issue_stage = [&](int ti) {
        const int i0  = ti * SI;
        const int buf = ti & 1;
        #pragma unroll
        for (int h = 0; h < 2; h++) {
            const int p   = t + h * 512;         // 0..1023 float4 slots
            const int row = p >> 6;
            const int c4  = p & 63;
            cp16(stg_base + (uint32_t)(((buf * SI + row) * (DD / 4) + c4) * 16),
                 xb + (size_t)(i0 + row) * DD + c4 * 4);
        }
        asm volatile("cp.async.commit_group;");
    };

    issue_stage(0);
    issue_stage(1);

    float4 acc[RR][8];
    #pragma unroll
    for (int r = 0; r < RR; r++)
        #pragma unroll
        for (int q = 0; q < 8; q++)
            acc[r][q] = make_float4(0.f, 0.f, 0.f, 0.f);

    for (int ti = 0; ti < NTI; ti++) {
        asm volatile("cp.async.wait_group 1;");
        __syncthreads();
        const int buf = ti & 1;
        const int wi  = ti >> 1;
        const int sh  = (ti & 1) * 16;

        #pragma unroll
        for (int r = 0; r < RR; r++) {
            uint32_t w = (sbits[jl][r][wi] >> sh) & 0xffffu;
            while (w) {
                const int i = __ffs(w) - 1;
                w &= w - 1;
                const float4* __restrict__ src = &stg[buf][i][cg];
                #pragma unroll
                for (int q = 0; q < 8; q++) {
                    const float4 v = src[q * 8];
                    acc[r][q].x += v.x; acc[r][q].y += v.y;
                    acc[r][q].z += v.z; acc[r][q].w += v.w;
                }
            }
        }
        __syncthreads();
        if (ti + 2 < NTI) issue_stage(ti + 2);
    }

    // write tf32 into acat segments
    uint32_t* __restrict__ base =
        g_acat + (size_t)layer * ACAT_L + (obase + jl) * K_TOTAL;
    #pragma unroll
    for (int r = 0; r < RR; r++) {
        const float inv = sinv[jl][r];
        #pragma unroll
        for (int q = 0; q < 8; q++) {
            uint4 u;
            u.x = f2tf32(acc[r][q].x * inv);
            u.y = f2tf32(acc[r][q].y * inv);
            u.z = f2tf32(acc[r][q].z * inv);
            u.w = f2tf32(acc[r][q].w * inv);
            *(uint4*)&base[(r + 1) * DD + (q * 8 + cg) * 4] = u;
        }
    }
}

// ---------------------------------------------------------------------------
// Kernel 5: TF32 tensor-core GEMM + bias + ELU, cp.async 3-stage pipeline.
//   out[m,e] = elu( Acat[m,:] @ W[:,e] + bias[e] )
// M=8192, K=768, N=256. Block tile 64x128, 4 warps (2M x 2N), warp 32x64.
// ---------------------------------------------------------------------------
__device__ __forceinline__ void mma_tf32(float c[4], const uint32_t a[4],
                                         uint32_t b0, uint32_t b1) {
    asm volatile(
        "mma.sync.aligned.m16n8k8.row.col.f32.tf32.tf32.f32 "
        "{%0,%1,%2,%3}, {%4,%5,%6,%7}, {%8,%9}, {%0,%1,%2,%3};"
        : "+f"(c[0]), "+f"(c[1]), "+f"(c[2]), "+f"(c[3])
        : "r"(a[0]), "r"(a[1]), "r"(a[2]), "r"(a[3]), "r"(b0), "r"(b1));
}

#define ASTR 20    // A shared stride (floats)
#define BSTR 132   // B shared stride (floats)

__global__ void __launch_bounds__(128)
rgcn_gemm_kernel(int layer, const float* __restrict__ bias,
                 float* __restrict__ dout) {
    __shared__ uint32_t As[STG][64][ASTR];    // [stage][m][k]
    __shared__ uint32_t Bs[STG][BKT][BSTR];   // [stage][k][n]

    const uint32_t* __restrict__ Ag = g_acat + (size_t)layer * ACAT_L;
    const uint32_t* __restrict__ Bg = g_w + (size_t)layer * W_L;

    const int t    = threadIdx.x;
    const int lane = t & 31;
    const int wid  = t >> 5;
    const int wm   = wid & 1;
    const int wn   = wid >> 1;
    const int gid  = lane >> 2;
    const int tig  = lane & 3;
    const int m0   = blockIdx.y * 64;
    const int e0   = blockIdx.x * 128;

    const uint32_t asb = (uint32_t)__cvta_generic_to_shared(As);
    const uint32_t bsb = (uint32_t)__cvta_generic_to_shared(Bs);

    const int ar0 = t >> 2;
    const int ako = (t & 3) << 2;
    const int br0 = t >> 5;
    const int bno = (t & 31) << 2;

    auto issue_tile = [&](int tile) {
        if (tile < NT) {
            const int stage = tile % STG;
            const int kg = tile * BKT;
            #pragma unroll
            for (int i = 0; i < 2; i++) {
                const int r = ar0 + 32 * i;
                cp16(asb + (uint32_t)(((stage * 64 + r) * ASTR + ako) * 4),
                     Ag + (size_t)(m0 + r) * K_TOTAL + kg + ako);
            }
            #pragma unroll
            for (int i = 0; i < 4; i++) {
                const int r = br0 + 4 * i;
                cp16(bsb + (uint32_t)(((stage * BKT + r) * BSTR + bno) * 4),
                     Bg + (size_t)(kg + r) * DD + e0 + bno);
            }
        }
        asm volatile("cp.async.commit_group;");
    };

    issue_tile(0);
    issue_tile(1);

    float acc[2][8][4] = {};

    for (int kt = 0; kt < NT; kt++) {
        asm volatile("cp.async.wait_group %0;" :: "n"(STG - 2));
        __syncthreads();

        issue_tile(kt + STG - 1);

        const int st = kt % STG;
        #pragma unroll
        for (int ks = 0; ks < 2; ks++) {
            const int kb = ks * 8;
            uint32_t af[2][4];
            #pragma unroll
            for (int mt = 0; mt < 2; mt++) {
                const int m = wm * 32 + mt * 16 + gid;
                af[mt][0] = As[st][m][kb + tig];
                af[mt][1] = As[st][m + 8][kb + tig];
                af[mt][2] = As[st][m][kb + tig + 4];
                af[mt][3] = As[st][m + 8][kb + tig + 4];
            }
            #pragma unroll
            for (int nt = 0; nt < 8; nt++) {
                const int n = wn * 64 + nt * 8 + gid;
                const uint32_t b0 = Bs[st][kb + tig][n];
                const uint32_t b1 = Bs[st][kb + tig + 4][n];
                mma_tf32(acc[0][nt], af[0], b0, b1);
                mma_tf32(acc[1][nt], af[1], b0, b1);
            }
        }
    }

    // epilogue: bias + ELU
    float* __restrict__ outf = (layer == 0) ? (float*)g_h : dout;
    uint32_t* __restrict__ outt = g_acat + ACAT_L;   // layer-1 seg0
    const float2* __restrict__ bias2 = (const float2*)bias;

    #pragma unroll
    for (int mt = 0; mt < 2; mt++) {
        const int mrow = m0 + wm * 32 + mt * 16 + gid;
        #pragma unroll
        for (int nt = 0; nt < 8; nt++) {
            const int col = e0 + wn * 64 + nt * 8 + 2 * tig;
            const float2 bb = bias2[col >> 1];
            float v0 = acc[mt][nt][0] + bb.x;
            float v1 = acc[mt][nt][1] + bb.y;
            float v2 = acc[mt][nt][2] + bb.x;
            float v3 = acc[mt][nt][3] + bb.y;
            v0 = (v0 > 0.f) ? v0 : expm1f(v0);
            v1 = (v1 > 0.f) ? v1 : expm1f(v1);
            v2 = (v2 > 0.f) ? v2 : expm1f(v2);
            v3 = (v3 > 0.f) ? v3 : expm1f(v3);
            *(float2*)&outf[(size_t)mrow * DD + col]       = make_float2(v0, v1);
            *(float2*)&outf[(size_t)(mrow + 8) * DD + col] = make_float2(v2, v3);
            if (layer == 0) {
                uint2 u0; u0.x = f2tf32(v0); u0.y = f2tf32(v1);
                uint2 u1; u1.x = f2tf32(v2); u1.y = f2tf32(v3);
                *(uint2*)&outt[(size_t)mrow * K_TOTAL + col]       = u0;
                *(uint2*)&outt[(size_t)(mrow + 8) * K_TOTAL + col] = u1;
            }
        }
    }
}

// ---------------------------------------------------------------------------
// Launch: masks+bits+cvt once, then per layer: agg -> TF32 GEMM+bias+ELU.
// ---------------------------------------------------------------------------
extern "C" void kernel_launch(void* const* d_in, const int* in_sizes, int n_in,
                              void* d_out, int out_size) {
    const float* x       = (const float*)d_in[0];
    const float* w_rel1  = (const float*)d_in[1];
    const float* w_root1 = (const float*)d_in[2];
    const float* b1      = (const float*)d_in[3];
    const float* w_rel2  = (const float*)d_in[4];
    const float* w_root2 = (const float*)d_in[5];
    const float* b2      = (const float*)d_in[6];
    const int* aug   = (const int*)d_in[7];
    const int* punct = (const int*)d_in[8];
    float* out = (float*)d_out;

    build_masks_kernel<<<dim3(NN / 32, NN / 32, BS), dim3(32, 8)>>>(aug, punct);
    build_bits_kernel<<<dim3(NN, BS), 32>>>();
    cvt_inputs_kernel<<<1184, 256>>>(x, w_root1, w_rel1, w_root2, w_rel2);

    // Layer 1: agg(x) -> acat0 seg1/2; gemm -> g_h + acat1 seg0
    aggregate_kernel<<<dim3(NN / TJ, BS), 512>>>(x, 0);
    rgcn_gemm_kernel<<<dim3(DD / 128, M_TOTAL / 64), 128>>>(0, b1, nullptr);

    // Layer 2: agg(h) -> acat1 seg1/2; gemm -> out
    aggregate_kernel<<<dim3(NN / TJ, BS), 512>>>(nullptr, 1);
    rgcn_gemm_kernel<<<dim3(DD / 128, M_TOTAL / 64), 128>>>(1, b2, out);
}

// round 10
// speedup vs baseline: 1.3592x; 1.3592x over previous
#include <cuda_runtime.h>
#include <cuda_bf16.h>
#include <cstdint>

#define BS 16
#define NN 512
#define DD 256
#define RR 2
#define M_TOTAL (BS * NN)           // 8192
#define K_TOTAL (3 * DD)            // 768
#define BKT 16                      // GEMM K-tile
#define NT (K_TOTAL / BKT)          // 48 tiles
#define STG 3                       // GEMM cp.async stages
#define ACAT_L ((size_t)M_TOTAL * K_TOTAL)
#define W_L    ((size_t)K_TOTAL * DD)

// Scratch (no allocations allowed).
__device__ __align__(16) uint32_t g_bits[BS * NN][RR][NN / 32];        // per (b,j): source bitmaps
__device__ __align__(16) unsigned short g_list[(size_t)BS * NN * NN];  // per (b,j): r0 front, r1 back
__device__ int   g_cnt[RR][BS * NN];
__device__ float g_inv[RR][BS * NN];
__device__ __align__(16) uint32_t g_acat[2 * ACAT_L];   // tf32 [layer][m][768] = [x|agg0|agg1]
__device__ __align__(16) uint32_t g_w[2 * W_L];         // tf32 [layer][768][256]
__device__ __align__(16) float g_h[(size_t)BS * NN * DD];   // layer-1 output (fp32)

__device__ __forceinline__ uint32_t f2tf32(float f) {
    uint32_t u;
    asm("cvt.rna.tf32.f32 %0, %1;" : "=r"(u) : "f"(f));
    return u;
}

__device__ __forceinline__ void cp16(uint32_t dst, const void* src) {
    asm volatile("cp.async.cg.shared.global [%0], [%1], 16;"
                 :: "r"(dst), "l"(src));
}

// ---------------------------------------------------------------------------
// Kernel 1: fused mask + bitmap build. Adjacency is int32 on device (JAX
// downcasts int64). bit0 = punct (punct==1 && aug!=1), bit1 = aug (aug==1).
// 32x32 tile transpose in shared, then per-j ballots over i produce the
// 32-bit words of g_bits directly (no byte-mask intermediate).
// ---------------------------------------------------------------------------
__global__ void build_bits_kernel(const int* __restrict__ aug,
                                  const int* __restrict__ punct) {
    __shared__ unsigned char tile[32][33];
    const int b  = blockIdx.z;
    const int i0 = blockIdx.y * 32;
    const int j0 = blockIdx.x * 32;
    const int tx = threadIdx.x;   // 32 (lane)
    const int ty = threadIdx.y;   // 8  (warp)
    const size_t base = (size_t)b * NN * NN;

    #pragma unroll
    for (int s = 0; s < 4; s++) {
        const int ii = ty + s * 8;
        const size_t idx = base + (size_t)(i0 + ii) * NN + (j0 + tx);
        const int a = aug[idx];
        const int p = punct[idx];
        tile[ii][tx] = (a == 1) ? (unsigned char)2
                                : ((p == 1) ? (unsigned char)1 : (unsigned char)0);
    }
    __syncthreads();
    #pragma unroll
    for (int s = 0; s < 4; s++) {
        const int jj = ty + s * 8;
        const unsigned char m = tile[tx][jj];   // lane = i within tile
        const unsigned b0 = __ballot_sync(0xffffffffu, m & 1);
        const unsigned b1 = __ballot_sync(0xffffffffu, m & 2);
        if (tx == 0) {
            const size_t o = (size_t)b * NN + j0 + jj;
            g_bits[o][0][i0 >> 5] = b0;
            g_bits[o][1][i0 >> 5] = b1;
        }
    }
}

// ---------------------------------------------------------------------------
// Kernel 2: compact neighbor lists from bitmaps. One warp per (b,j).
// Lane l (<16) owns i-word l; warp shfl-scan gives list offsets.
// ---------------------------------------------------------------------------
__global__ void __launch_bounds__(32)
build_lists_kernel() {
    const int j = blockIdx.x;
    const int b = blockIdx.y;
    const int lane = threadIdx.x;
    const size_t o = (size_t)b * NN + j;

    uint32_t w0 = 0, w1 = 0;
    if (lane < NN / 32) {
        w0 = g_bits[o][0][lane];
        w1 = g_bits[o][1][lane];
    }
    const int c0 = __popc(w0);
    const int c1 = __popc(w1);

    int s0 = c0, s1 = c1;
    #pragma unroll
    for (int d = 1; d < 32; d <<= 1) {
        const int t0 = __shfl_up_sync(0xffffffffu, s0, d);
        const int t1 = __shfl_up_sync(0xffffffffu, s1, d);
        if (lane >= d) { s0 += t0; s1 += t1; }
    }
    int off0 = s0 - c0;
    int off1 = s1 - c1;
    const int tot0 = __shfl_sync(0xffffffffu, s0, 31);
    const int tot1 = __shfl_sync(0xffffffffu, s1, 31);

    unsigned short* __restrict__ lst = g_list + o * NN;
    const int ibase = lane * 32;
    while (w0) {
        const int i = __ffs(w0) - 1;
        w0 &= w0 - 1;
        lst[off0++] = (unsigned short)(ibase + i);
    }
    while (w1) {
        const int i = __ffs(w1) - 1;
        w1 &= w1 - 1;
        lst[NN - 1 - off1] = (unsigned short)(ibase + i);
        off1++;
    }
    if (lane == 0) {
        g_cnt[0][o] = tot0;
        g_cnt[1][o] = tot1;
        g_inv[0][o] = 1.0f / (float)max(tot0, 1);
        g_inv[1][o] = 1.0f / (float)max(tot1, 1);
    }
}

// ---------------------------------------------------------------------------
// Kernel 3: convert x and both layers' weights to tf32 concat layouts.
// ---------------------------------------------------------------------------
#define XF4 (M_TOTAL * DD / 4)
#define WF4L (K_TOTAL * DD / 4)
#define ROOTF4 (DD * DD / 4)

__global__ void cvt_inputs_kernel(const float* __restrict__ x,
                                  const float* __restrict__ wroot1,
                                  const float* __restrict__ wrel1,
                                  const float* __restrict__ wroot2,
                                  const float* __restrict__ wrel2) {
    const int total = XF4 + 2 * WF4L;
    for (int idx = blockIdx.x * blockDim.x + threadIdx.x; idx < total;
         idx += gridDim.x * blockDim.x) {
        float4 v;
        uint32_t* dst;
        if (idx < XF4) {
            const int m = idx >> 6;
            const int dq = idx & 63;
            v = ((const float4*)x)[idx];
            dst = g_acat + (size_t)m * K_TOTAL + dq * 4;
        } else {
            const int j = idx - XF4;
            const int L = j / WF4L;
            const int j2 = j - L * WF4L;
            const float4* src = (j2 < ROOTF4)
                ? ((const float4*)(L ? wroot2 : wroot1)) + j2
                : ((const float4*)(L ? wrel2 : wrel1)) + (j2 - ROOTF4);
            v = *src;
            dst = g_w + (size_t)L * W_L + (size_t)j2 * 4;
        }
        uint4 u;
        u.x = f2tf32(v.x); u.y = f2tf32(v.y);
        u.z = f2tf32(v.z); u.w = f2tf32(v.w);
        *(uint4*)dst = u;
    }
}

// ---------------------------------------------------------------------------
// Kernel 4: sparse mean-aggregation via compact lists (round-8 proven form).
// Block = (j, b), 64 threads; thread owns channels [4t,4t+3] (float4).
// x4 unroll, packed index loads, dual accumulators. Writes tf32 into
// g_acat[layer] segments 1 and 2.
// ---------------------------------------------------------------------------
__global__ void __launch_bounds__(64)
aggregate_kernel(const float* __restrict__ x, int layer) {
    const int j = blockIdx.x;
    const int b = blockIdx.y;
    const int t = threadIdx.x;
    const size_t o = (size_t)b * NN + j;

    __shared__ alignas(8) unsigned short slist[NN];
    __shared__ int sn0, sn1;
    __shared__ float si0, si1;
    if (t == 0) {
        sn0 = g_cnt[0][o]; sn1 = g_cnt[1][o];
        si0 = g_inv[0][o]; si1 = g_inv[1][o];
    }
    const unsigned short* __restrict__ lst = g_list + o * NN;
    #pragma unroll
    for (int k = 0; k < NN / 2 / 64; k++)
        ((unsigned int*)slist)[t + k * 64] = ((const unsigned int*)lst)[t + k * 64];
    __syncthreads();

    const int n0 = sn0, n1 = sn1;
    const float inv0 = si0, inv1 = si1;
    const float4* __restrict__ xb = (const float4*)(
        (layer ? (const float*)g_h : x) + (size_t)b * NN * DD);

    float4 p0 = make_float4(0.f, 0.f, 0.f, 0.f);
    float4 p1 = make_float4(0.f, 0.f, 0.f, 0.f);
    int k = 0;
    for (; k + 4 <= n0; k += 4) {
        const uint32_t w0 = *(const uint32_t*)&slist[k];
        const uint32_t w1 = *(const uint32_t*)&slist[k + 2];
        const float4 v0 = xb[(w0 & 0xffffu) * (DD / 4) + t];
        const float4 v1 = xb[(w0 >> 16)     * (DD / 4) + t];
        const float4 v2 = xb[(w1 & 0xffffu) * (DD / 4) + t];
        const float4 v3 = xb[(w1 >> 16)     * (DD / 4) + t];
        p0.x += v0.x + v2.x; p0.y += v0.y + v2.y;
        p0.z += v0.z + v2.z; p0.w += v0.w + v2.w;
        p1.x += v1.x + v3.x; p1.y += v1.y + v3.y;
        p1.z += v1.z + v3.z; p1.w += v1.w + v3.w;
    }
    for (; k < n0; k++) {
        const float4 v = xb[slist[k] * (DD / 4) + t];
        p0.x += v.x; p0.y += v.y; p0.z += v.z; p0.w += v.w;
    }
    float4 a0 = make_float4(p0.x + p1.x, p0.y + p1.y, p0.z + p1.z, p0.w + p1.w);

    float4 q0 = make_float4(0.f, 0.f, 0.f, 0.f);
    float4 q1 = make_float4(0.f, 0.f, 0.f, 0.f);
    k = 0;
    for (; k + 4 <= n1; k += 4) {
        const int i0 = slist[NN - 1 - k];
        const int i1 = slist[NN - 2 - k];
        const int i2 = slist[NN - 3 - k];
        const int i3 = slist[NN - 4 - k];
        const float4 v0 = xb[i0 * (DD / 4) + t];
        const float4 v1 = xb[i1 * (DD / 4) + t];
        const float4 v2 = xb[i2 * (DD / 4) + t];
        const float4 v3 = xb[i3 * (DD / 4) + t];
        q0.x += v0.x + v2.x; q0.y += v0.y + v2.y;
        q0.z += v0.z + v2.z; q0.w += v0.w + v2.w;
        q1.x += v1.x + v3.x; q1.y += v1.y + v3.y;
        q1.z += v1.z + v3.z; q1.w += v1.w + v3.w;
    }
    for (; k < n1; k++) {
        const float4 v = xb[slist[NN - 1 - k] * (DD / 4) + t];
        q0.x += v.x; q0.y += v.y; q0.z += v.z; q0.w += v.w;
    }
    float4 a1 = make_float4(q0.x + q1.x, q0.y + q1.y, q0.z + q1.z, q0.w + q1.w);

    uint32_t* __restrict__ base =
        g_acat + (size_t)layer * ACAT_L + o * K_TOTAL;
    uint4 u0, u1;
    u0.x = f2tf32(a0.x * inv0); u0.y = f2tf32(a0.y * inv0);
    u0.z = f2tf32(a0.z * inv0); u0.w = f2tf32(a0.w * inv0);
    u1.x = f2tf32(a1.x * inv1); u1.y = f2tf32(a1.y * inv1);
    u1.z = f2tf32(a1.z * inv1); u1.w = f2tf32(a1.w * inv1);
    ((uint4*)(base + DD))[t]     = u0;
    ((uint4*)(base + 2 * DD))[t] = u1;
}

// ---------------------------------------------------------------------------
// Kernel 5: TF32 tensor-core GEMM + bias + ELU, cp.async 3-stage pipeline.
//   out[m,e] = elu( Acat[m,:] @ W[:,e] + bias[e] )
// M=8192, K=768, N=256. Block tile 64x128, 4 warps (2M x 2N), warp 32x64.
// ---------------------------------------------------------------------------
__device__ __forceinline__ void mma_tf32(float c[4], const uint32_t a[4],
                                         uint32_t b0, uint32_t b1) {
    asm volatile(
        "mma.sync.aligned.m16n8k8.row.col.f32.tf32.tf32.f32 "
        "{%0,%1,%2,%3}, {%4,%5,%6,%7}, {%8,%9}, {%0,%1,%2,%3};"
        : "+f"(c[0]), "+f"(c[1]), "+f"(c[2]), "+f"(c[3])
        : "r"(a[0]), "r"(a[1]), "r"(a[2]), "r"(a[3]), "r"(b0), "r"(b1));
}

#define ASTR 20
#define BSTR 132

__global__ void __launch_bounds__(128)
rgcn_gemm_kernel(int layer, const float* __restrict__ bias,
                 float* __restrict__ dout) {
    __shared__ uint32_t As[STG][64][ASTR];
    __shared__ uint32_t Bs[STG][BKT][BSTR];

    const uint32_t* __restrict__ Ag = g_acat + (size_t)layer * ACAT_L;
    const uint32_t* __restrict__ Bg = g_w + (size_t)layer * W_L;

    const int t    = threadIdx.x;
    const int lane = t & 31;
    const int wid  = t >> 5;
    const int wm   = wid & 1;
    const int wn   = wid >> 1;
    const int gid  = lane >> 2;
    const int tig  = lane & 3;
    const int m0   = blockIdx.y * 64;
    const int e0   = blockIdx.x * 128;

    const uint32_t asb = (uint32_t)__cvta_generic_to_shared(As);
    const uint32_t bsb = (uint32_t)__cvta_generic_to_shared(Bs);

    const int ar0 = t >> 2;
    const int ako = (t & 3) << 2;
    const int br0 = t >> 5;
    const int bno = (t & 31) << 2;

    auto issue_tile = [&](int tile) {
        if (tile < NT) {
            const int stage = tile % STG;
            const int kg = tile * BKT;
            #pragma unroll
            for (int i = 0; i < 2; i++) {
                const int r = ar0 + 32 * i;
                cp16(asb + (uint32_t)(((stage * 64 + r) * ASTR + ako) * 4),
                     Ag + (size_t)(m0 + r) * K_TOTAL + kg + ako);
            }
            #pragma unroll
            for (int i = 0; i < 4; i++) {
                const int r = br0 + 4 * i;
                cp16(bsb + (uint32_t)(((stage * BKT + r) * BSTR + bno) * 4),
                     Bg + (size_t)(kg + r) * DD + e0 + bno);
            }
        }
        asm volatile("cp.async.commit_group;");
    };

    issue_tile(0);
    issue_tile(1);

    float acc[2][8][4] = {};

    for (int kt = 0; kt < NT; kt++) {
        asm volatile("cp.async.wait_group %0;" :: "n"(STG - 2));
        __syncthreads();

        issue_tile(kt + STG - 1);

        const int st = kt % STG;
        #pragma unroll
        for (int ks = 0; ks < 2; ks++) {
            const int kb = ks * 8;
            uint32_t af[2][4];
            #pragma unroll
            for (int mt = 0; mt < 2; mt++) {
                const int m = wm * 32 + mt * 16 + gid;
                af[mt][0] = As[st][m][kb + tig];
                af[mt][1] = As[st][m + 8][kb + tig];
                af[mt][2] = As[st][m][kb + tig + 4];
                af[mt][3] = As[st][m + 8][kb + tig + 4];
            }
            #pragma unroll
            for (int nt = 0; nt < 8; nt++) {
                const int n = wn * 64 + nt * 8 + gid;
                const uint32_t b0 = Bs[st][kb + tig][n];
                const uint32_t b1 = Bs[st][kb + tig + 4][n];
                mma_tf32(acc[0][nt], af[0], b0, b1);
                mma_tf32(acc[1][nt], af[1], b0, b1);
            }
        }
    }

    float* __restrict__ outf = (layer == 0) ? (float*)g_h : dout;
    uint32_t* __restrict__ outt = g_acat + ACAT_L;
    const float2* __restrict__ bias2 = (const float2*)bias;

    #pragma unroll
    for (int mt = 0; mt < 2; mt++) {
        const int mrow = m0 + wm * 32 + mt * 16 + gid;
        #pragma unroll
        for (int nt = 0; nt < 8; nt++) {
            const int col = e0 + wn * 64 + nt * 8 + 2 * tig;
            const float2 bb = bias2[col >> 1];
            float v0 = acc[mt][nt][0] + bb.x;
            float v1 = acc[mt][nt][1] + bb.y;
            float v2 = acc[mt][nt][2] + bb.x;
            float v3 = acc[mt][nt][3] + bb.y;
            v0 = (v0 > 0.f) ? v0 : expm1f(v0);
            v1 = (v1 > 0.f) ? v1 : expm1f(v1);
            v2 = (v2 > 0.f) ? v2 : expm1f(v2);
            v3 = (v3 > 0.f) ? v3 : expm1f(v3);
            *(float2*)&outf[(size_t)mrow * DD + col]       = make_float2(v0, v1);
            *(float2*)&outf[(size_t)(mrow + 8) * DD + col] = make_float2(v2, v3);
            if (layer == 0) {
                uint2 u0; u0.x = f2tf32(v0); u0.y = f2tf32(v1);
                uint2 u1; u1.x = f2tf32(v2); u1.y = f2tf32(v3);
                *(uint2*)&outt[(size_t)mrow * K_TOTAL + col]       = u0;
                *(uint2*)&outt[(size_t)(mrow + 8) * K_TOTAL + col] = u1;
            }
        }
    }
}

// ---------------------------------------------------------------------------
// Launch: bits+lists+cvt once, then per layer: agg -> TF32 GEMM+bias+ELU.
// ---------------------------------------------------------------------------
extern "C" void kernel_launch(void* const* d_in, const int* in_sizes, int n_in,
                              void* d_out, int out_size) {
    const float* x       = (const float*)d_in[0];
    const float* w_rel1  = (const float*)d_in[1];
    const float* w_root1 = (const float*)d_in[2];
    const float* b1      = (const float*)d_in[3];
    const float* w_rel2  = (const float*)d_in[4];
    const float* w_root2 = (const float*)d_in[5];
    const float* b2      = (const float*)d_in[6];
    const int* aug   = (const int*)d_in[7];
    const int* punct = (const int*)d_in[8];
    float* out = (float*)d_out;

    build_bits_kernel<<<dim3(NN / 32, NN / 32, BS), dim3(32, 8)>>>(aug, punct);
    build_lists_kernel<<<dim3(NN, BS), 32>>>();
    cvt_inputs_kernel<<<1184, 256>>>(x, w_root1, w_rel1, w_root2, w_rel2);

    // Layer 1
    aggregate_kernel<<<dim3(NN, BS), 64>>>(x, 0);
    rgcn_gemm_kernel<<<dim3(DD / 128, M_TOTAL / 64), 128>>>(0, b1, nullptr);

    // Layer 2
    aggregate_kernel<<<dim3(NN, BS), 64>>>(nullptr, 1);
    rgcn_gemm_kernel<<<dim3(DD / 128, M_TOTAL / 64), 128>>>(1, b2, out);
}

// round 11
// speedup vs baseline: 1.3990x; 1.0293x over previous
#include <cuda_runtime.h>
#include <cuda_bf16.h>
#include <cstdint>

#define BS 16
#define NN 512
#define DD 256
#define RR 2
#define M_TOTAL (BS * NN)           // 8192
#define K_TOTAL (3 * DD)            // 768
#define BKT 16                      // GEMM K-tile
#define NT (K_TOTAL / BKT)          // 48 tiles
#define STG 3                       // GEMM cp.async stages
#define ACAT_L ((size_t)M_TOTAL * K_TOTAL)
#define W_L    ((size_t)K_TOTAL * DD)

// Scratch (no allocations allowed).
__device__ __align__(16) unsigned short g_list[(size_t)BS * NN * NN];  // per (b,j): r0 front, r1 back
__device__ int   g_cnt[RR][BS * NN];
__device__ float g_inv[RR][BS * NN];
__device__ __align__(16) uint32_t g_acat[2 * ACAT_L];   // tf32 [layer][m][768] = [x|agg0|agg1]
__device__ __align__(16) uint32_t g_w[2 * W_L];         // tf32 [layer][768][256]
__device__ __align__(16) float g_h[(size_t)BS * NN * DD];   // layer-1 output (fp32)

__device__ __forceinline__ uint32_t f2tf32(float f) {
    uint32_t u;
    asm("cvt.rna.tf32.f32 %0, %1;" : "=r"(u) : "f"(f));
    return u;
}

__device__ __forceinline__ void cp16(uint32_t dst, const void* src) {
    asm volatile("cp.async.cg.shared.global [%0], [%1], 16;"
                 :: "r"(dst), "l"(src));
}

// ---------------------------------------------------------------------------
// Kernel 1: fused mask transpose + compact neighbor-list build.
// Adjacency is int32 on device (JAX downcasts int64).
// bit0 = punct (punct==1 && aug!=1), bit1 = aug (aug==1). Disjoint relations
// share one 512-slot list per (b,j): r0 from the front, r1 from the back.
// Block = (32-j tile, b), 256 threads (8 warps).
//   Stage 1: warp w reads rows i in [w*64, w*64+64) x 32 j's (coalesced 128B),
//            stores mask bytes transposed into smem (row stride 516 ->
//            conflict-free byte stores).
//   Stage 2: warp w scans j-locals w*4..w*4+3 with ballots, emits lists.
// ---------------------------------------------------------------------------
#define SMROW 516

__global__ void __launch_bounds__(256)
build_lists_kernel(const int* __restrict__ aug,
                   const int* __restrict__ punct) {
    __shared__ unsigned char sm[32 * SMROW];
    const int jt = blockIdx.x;          // j-tile
    const int b  = blockIdx.y;
    const int t  = threadIdx.x;
    const int w  = t >> 5;              // warp 0..7
    const int lane = t & 31;
    const int j0 = jt * 32;
    const size_t base = (size_t)b * NN * NN;

    // Stage 1: transpose mask bytes into smem
    const int i0w = w * 64;
    #pragma unroll 4
    for (int s = 0; s < 64; s++) {
        const int i = i0w + s;
        const size_t idx = base + (size_t)i * NN + j0 + lane;
        const int a = aug[idx];
        const int p = punct[idx];
        sm[lane * SMROW + i] = (a == 1) ? (unsigned char)2
                                        : ((p == 1) ? (unsigned char)1
                                                    : (unsigned char)0);
    }
    __syncthreads();

    // Stage 2: build lists for 4 j's per warp
    const unsigned lt = (1u << lane) - 1u;
    #pragma unroll
    for (int q = 0; q < 4; q++) {
        const int jl = w * 4 + q;
        const unsigned char* __restrict__ row = sm + jl * SMROW;
        const size_t o = (size_t)b * NN + j0 + jl;
        unsigned short* __restrict__ lst = g_list + o * NN;

        int c0 = 0, c1 = 0;
        #pragma unroll 4
        for (int s = 0; s < NN; s += 32) {
            const unsigned char m = row[s + lane];
            const unsigned b0 = __ballot_sync(0xffffffffu, m & 1);
            const unsigned b1 = __ballot_sync(0xffffffffu, m & 2);
            if (m & 1) lst[c0 + __popc(b0 & lt)] = (unsigned short)(s + lane);
            if (m & 2) lst[NN - 1 - (c1 + __popc(b1 & lt))] = (unsigned short)(s + lane);
            c0 += __popc(b0);
            c1 += __popc(b1);
        }
        if (lane == 0) {
            g_cnt[0][o] = c0;
            g_cnt[1][o] = c1;
            g_inv[0][o] = 1.0f / (float)max(c0, 1);
            g_inv[1][o] = 1.0f / (float)max(c1, 1);
        }
    }
}

// ---------------------------------------------------------------------------
// Kernel 2: convert x and both layers' weights to tf32 concat layouts.
// ---------------------------------------------------------------------------
#define XF4 (M_TOTAL * DD / 4)
#define WF4L (K_TOTAL * DD / 4)
#define ROOTF4 (DD * DD / 4)

__global__ void cvt_inputs_kernel(const float* __restrict__ x,
                                  const float* __restrict__ wroot1,
                                  const float* __restrict__ wrel1,
                                  const float* __restrict__ wroot2,
                                  const float* __restrict__ wrel2) {
    const int total = XF4 + 2 * WF4L;
    for (int idx = blockIdx.x * blockDim.x + threadIdx.x; idx < total;
         idx += gridDim.x * blockDim.x) {
        float4 v;
        uint32_t* dst;
        if (idx < XF4) {
            const int m = idx >> 6;
            const int dq = idx & 63;
            v = ((const float4*)x)[idx];
            dst = g_acat + (size_t)m * K_TOTAL + dq * 4;
        } else {
            const int j = idx - XF4;
            const int L = j / WF4L;
            const int j2 = j - L * WF4L;
            const float4* src = (j2 < ROOTF4)
                ? ((const float4*)(L ? wroot2 : wroot1)) + j2
                : ((const float4*)(L ? wrel2 : wrel1)) + (j2 - ROOTF4);
            v = *src;
            dst = g_w + (size_t)L * W_L + (size_t)j2 * 4;
        }
        uint4 u;
        u.x = f2tf32(v.x); u.y = f2tf32(v.y);
        u.z = f2tf32(v.z); u.w = f2tf32(v.w);
        *(uint4*)dst = u;
    }
}

// ---------------------------------------------------------------------------
// Kernel 3: sparse mean-aggregation via compact lists (proven form).
// Block = (j, b), 64 threads; thread owns channels [4t,4t+3] (float4).
// x4 unroll, packed index loads, dual accumulators. Writes tf32 into
// g_acat[layer] segments 1 and 2.
// ---------------------------------------------------------------------------
__global__ void __launch_bounds__(64)
aggregate_kernel(const float* __restrict__ x, int layer) {
    const int j = blockIdx.x;
    const int b = blockIdx.y;
    const int t = threadIdx.x;
    const size_t o = (size_t)b * NN + j;

    __shared__ alignas(8) unsigned short slist[NN];
    __shared__ int sn0, sn1;
    __shared__ float si0, si1;
    if (t == 0) {
        sn0 = g_cnt[0][o]; sn1 = g_cnt[1][o];
        si0 = g_inv[0][o]; si1 = g_inv[1][o];
    }
    const unsigned short* __restrict__ lst = g_list + o * NN;
    #pragma unroll
    for (int k = 0; k < NN / 2 / 64; k++)
        ((unsigned int*)slist)[t + k * 64] = ((const unsigned int*)lst)[t + k * 64];
    __syncthreads();

    const int n0 = sn0, n1 = sn1;
    const float inv0 = si0, inv1 = si1;
    const float4* __restrict__ xb = (const float4*)(
        (layer ? (const float*)g_h : x) + (size_t)b * NN * DD);

    float4 p0 = make_float4(0.f, 0.f, 0.f, 0.f);
    float4 p1 = make_float4(0.f, 0.f, 0.f, 0.f);
    int k = 0;
    for (; k + 4 <= n0; k += 4) {
        const uint32_t w0 = *(const uint32_t*)&slist[k];
        const uint32_t w1 = *(const uint32_t*)&slist[k + 2];
        const float4 v0 = xb[(w0 & 0xffffu) * (DD / 4) + t];
        const float4 v1 = xb[(w0 >> 16)     * (DD / 4) + t];
        const float4 v2 = xb[(w1 & 0xffffu) * (DD / 4) + t];
        const float4 v3 = xb[(w1 >> 16)     * (DD / 4) + t];
        p0.x += v0.x + v2.x; p0.y += v0.y + v2.y;
        p0.z += v0.z + v2.z; p0.w += v0.w + v2.w;
        p1.x += v1.x + v3.x; p1.y += v1.y + v3.y;
        p1.z += v1.z + v3.z; p1.w += v1.w + v3.w;
    }
    for (; k < n0; k++) {
        const float4 v = xb[slist[k] * (DD / 4) + t];
        p0.x += v.x; p0.y += v.y; p0.z += v.z; p0.w += v.w;
    }
    float4 a0 = make_float4(p0.x + p1.x, p0.y + p1.y, p0.z + p1.z, p0.w + p1.w);

    float4 q0 = make_float4(0.f, 0.f, 0.f, 0.f);
    float4 q1 = make_float4(0.f, 0.f, 0.f, 0.f);
    k = 0;
    for (; k + 4 <= n1; k += 4) {
        const int i0 = slist[NN - 1 - k];
        const int i1 = slist[NN - 2 - k];
        const int i2 = slist[NN - 3 - k];
        const int i3 = slist[NN - 4 - k];
        const float4 v0 = xb[i0 * (DD / 4) + t];
        const float4 v1 = xb[i1 * (DD / 4) + t];
        const float4 v2 = xb[i2 * (DD / 4) + t];
        const float4 v3 = xb[i3 * (DD / 4) + t];
        q0.x += v0.x + v2.x; q0.y += v0.y + v2.y;
        q0.z += v0.z + v2.z; q0.w += v0.w + v2.w;
        q1.x += v1.x + v3.x; q1.y += v1.y + v3.y;
        q1.z += v1.z + v3.z; q1.w += v1.w + v3.w;
    }
    for (; k < n1; k++) {
        const float4 v = xb[slist[NN - 1 - k] * (DD / 4) + t];
        q0.x += v.x; q0.y += v.y; q0.z += v.z; q0.w += v.w;
    }
    float4 a1 = make_float4(q0.x + q1.x, q0.y + q1.y, q0.z + q1.z, q0.w + q1.w);

    uint32_t* __restrict__ base =
        g_acat + (size_t)layer * ACAT_L + o * K_TOTAL;
    uint4 u0, u1;
    u0.x = f2tf32(a0.x * inv0); u0.y = f2tf32(a0.y * inv0);
    u0.z = f2tf32(a0.z * inv0); u0.w = f2tf32(a0.w * inv0);
    u1.x = f2tf32(a1.x * inv1); u1.y = f2tf32(a1.y * inv1);
    u1.z = f2tf32(a1.z * inv1); u1.w = f2tf32(a1.w * inv1);
    ((uint4*)(base + DD))[t]     = u0;
    ((uint4*)(base + 2 * DD))[t] = u1;
}

// ---------------------------------------------------------------------------
// Kernel 4: TF32 tensor-core GEMM + bias + ELU, cp.async 3-stage pipeline.
//   out[m,e] = elu( Acat[m,:] @ W[:,e] + bias[e] )
// M=8192, K=768, N=256. Block tile 64x128, 4 warps (2M x 2N), warp 32x64.
// BSTR=136: B fragment bank = (8*tig + gid) % 32 -> conflict-free.
// ---------------------------------------------------------------------------
__device__ __forceinline__ void mma_tf32(float c[4], const uint32_t a[4],
                                         uint32_t b0, uint32_t b1) {
    asm volatile(
        "mma.sync.aligned.m16n8k8.row.col.f32.tf32.tf32.f32 "
        "{%0,%1,%2,%3}, {%4,%5,%6,%7}, {%8,%9}, {%0,%1,%2,%3};"
        : "+f"(c[0]), "+f"(c[1]), "+f"(c[2]), "+f"(c[3])
        : "r"(a[0]), "r"(a[1]), "r"(a[2]), "r"(a[3]), "r"(b0), "r"(b1));
}

#define ASTR 20
#define BSTR 136

__global__ void __launch_bounds__(128)
rgcn_gemm_kernel(int layer, const float* __restrict__ bias,
                 float* __restrict__ dout) {
    __shared__ uint32_t As[STG][64][ASTR];
    __shared__ uint32_t Bs[STG][BKT][BSTR];

    const uint32_t* __restrict__ Ag = g_acat + (size_t)layer * ACAT_L;
    const uint32_t* __restrict__ Bg = g_w + (size_t)layer * W_L;

    const int t    = threadIdx.x;
    const int lane = t & 31;
    const int wid  = t >> 5;
    const int wm   = wid & 1;
    const int wn   = wid >> 1;
    const int gid  = lane >> 2;
    const int tig  = lane & 3;
    const int m0   = blockIdx.y * 64;
    const int e0   = blockIdx.x * 128;

    const uint32_t asb = (uint32_t)__cvta_generic_to_shared(As);
    const uint32_t bsb = (uint32_t)__cvta_generic_to_shared(Bs);

    const int ar0 = t >> 2;
    const int ako = (t & 3) << 2;
    const int br0 = t >> 5;
    const int bno = (t & 31) << 2;

    auto issue_tile = [&](int tile) {
        if (tile < NT) {
            const int stage = tile % STG;
            const int kg = tile * BKT;
            #pragma unroll
            for (int i = 0; i < 2; i++) {
                const int r = ar0 + 32 * i;
                cp16(asb + (uint32_t)(((stage * 64 + r) * ASTR + ako) * 4),
                     Ag + (size_t)(m0 + r) * K_TOTAL + kg + ako);
            }
            #pragma unroll
            for (int i = 0; i < 4; i++) {
                const int r = br0 + 4 * i;
                cp16(bsb + (uint32_t)(((stage * BKT + r) * BSTR + bno) * 4),
                     Bg + (size_t)(kg + r) * DD + e0 + bno);
            }
        }
        asm volatile("cp.async.commit_group;");
    };

    issue_tile(0);
    issue_tile(1);

    float acc[2][8][4] = {};

    for (int kt = 0; kt < NT; kt++) {
        asm volatile("cp.async.wait_group %0;" :: "n"(STG - 2));
        __syncthreads();

        issue_tile(kt + STG - 1);

        const int st = kt % STG;
        #pragma unroll
        for (int ks = 0; ks < 2; ks++) {
            const int kb = ks * 8;
            uint32_t af[2][4];
            #pragma unroll
            for (int mt = 0; mt < 2; mt++) {
                const int m = wm * 32 + mt * 16 + gid;
                af[mt][0] = As[st][m][kb + tig];
                af[mt][1] = As[st][m + 8][kb + tig];
                af[mt][2] = As[st][m][kb + tig + 4];
                af[mt][3] = As[st][m + 8][kb + tig + 4];
            }
            #pragma unroll
            for (int nt = 0; nt < 8; nt++) {
                const int n = wn * 64 + nt * 8 + gid;
                const uint32_t b0 = Bs[st][kb + tig][n];
                const uint32_t b1 = Bs[st][kb + tig + 4][n];
                mma_tf32(acc[0][nt], af[0], b0, b1);
                mma_tf32(acc[1][nt], af[1], b0, b1);
            }
        }
    }

    float* __restrict__ outf = (layer == 0) ? (float*)g_h : dout;
    uint32_t* __restrict__ outt = g_acat + ACAT_L;
    const float2* __restrict__ bias2 = (const float2*)bias;

    #pragma unroll
    for (int mt = 0; mt < 2; mt++) {
        const int mrow = m0 + wm * 32 + mt * 16 + gid;
        #pragma unroll
        for (int nt = 0; nt < 8; nt++) {
            const int col = e0 + wn * 64 + nt * 8 + 2 * tig;
            const float2 bb = bias2[col >> 1];
            float v0 = acc[mt][nt][0] + bb.x;
            float v1 = acc[mt][nt][1] + bb.y;
            float v2 = acc[mt][nt][2] + bb.x;
            float v3 = acc[mt][nt][3] + bb.y;
            v0 = (v0 > 0.f) ? v0 : expm1f(v0);
            v1 = (v1 > 0.f) ? v1 : expm1f(v1);
            v2 = (v2 > 0.f) ? v2 : expm1f(v2);
            v3 = (v3 > 0.f) ? v3 : expm1f(v3);
            *(float2*)&outf[(size_t)mrow * DD + col]       = make_float2(v0, v1);
            *(float2*)&outf[(size_t)(mrow + 8) * DD + col] = make_float2(v2, v3);
            if (layer == 0) {
                uint2 u0; u0.x = f2tf32(v0); u0.y = f2tf32(v1);
                uint2 u1; u1.x = f2tf32(v2); u1.y = f2tf32(v3);
                *(uint2*)&outt[(size_t)mrow * K_TOTAL + col]       = u0;
                *(uint2*)&outt[(size_t)(mrow + 8) * K_TOTAL + col] = u1;
            }
        }
    }
}

// ---------------------------------------------------------------------------
// Launch: lists+cvt once, then per layer: agg -> TF32 GEMM+bias+ELU.
// ---------------------------------------------------------------------------
extern "C" void kernel_launch(void* const* d_in, const int* in_sizes, int n_in,
                              void* d_out, int out_size) {
    const float* x       = (const float*)d_in[0];
    const float* w_rel1  = (const float*)d_in[1];
    const float* w_root1 = (const float*)d_in[2];
    const float* b1      = (const float*)d_in[3];
    const float* w_rel2  = (const float*)d_in[4];
    const float* w_root2 = (const float*)d_in[5];
    const float* b2      = (const float*)d_in[6];
    const int* aug   = (const int*)d_in[7];
    const int* punct = (const int*)d_in[8];
    float* out = (float*)d_out;

    build_lists_kernel<<<dim3(NN / 32, BS), 256>>>(aug, punct);
    cvt_inputs_kernel<<<1184, 256>>>(x, w_root1, w_rel1, w_root2, w_rel2);

    // Layer 1
    aggregate_kernel<<<dim3(NN, BS), 64>>>(x, 0);
    rgcn_gemm_kernel<<<dim3(DD / 128, M_TOTAL / 64), 128>>>(0, b1, nullptr);

    // Layer 2
    aggregate_kernel<<<dim3(NN, BS), 64>>>(nullptr, 1);
    rgcn_gemm_kernel<<<dim3(DD / 128, M_TOTAL / 64), 128>>>(1, b2, out);
}